// round 8
// baseline (speedup 1.0000x reference)
#include <cuda_runtime.h>
#include <math.h>

#define E    768
#define E2   1536
#define E3   2304
#define ULEN 256
#define NB   148
#define NTH  256

// ---------------- device scratch (no allocations allowed) ----------------
__device__ __align__(16) float g_WqT [E*E];
__device__ __align__(16) float g_WvT [E*E];
__device__ __align__(16) float g_WkT [E*E2];     // [o][i]
__device__ __align__(16) float g_WkvT[E*E2];     // [e][i]
__device__ __align__(16) float g_qall[ULEN*E];
__device__ __align__(16) float g_Pall[ULEN*E2];  // pre-scaled by 1/sqrt(E)
__device__ __align__(16) float g_call[ULEN];     // pre-scaled
__device__ __align__(16) float g_vz  [E];
__device__ __align__(16) float g_v   [ULEN*E];
__device__ __align__(16) float g_score[ULEN];
__device__ __align__(16) float g_att [E];
__device__ __align__(16) float g_gh  [4*E3];     // Whh@h + bhh for {sf, sb, gf, gb}
__device__ __align__(16) float g_so  [E2];
__device__ __align__(16) float g_sst [8*E2];     // speaker states [spk][dir][e]
__device__ __align__(16) float g_ghid[E2];       // global GRU carry [dir][e]
__device__ __align__(16) float g_buf [ULEN*E2];
__device__ unsigned           bar_cnt;
__device__ volatile unsigned  bar_gen;

__device__ __forceinline__ float wred(float v){
#pragma unroll
    for (int o = 16; o; o >>= 1) v += __shfl_xor_sync(0xffffffffu, v, o);
    return v;
}
__device__ __forceinline__ float sigm(float x){ return 1.0f/(1.0f + expf(-x)); }

__device__ __forceinline__ void gsync(){
    __syncthreads();
    if (threadIdx.x == 0){
        __threadfence();
        unsigned g = bar_gen;
        if (atomicAdd(&bar_cnt, 1u) == gridDim.x - 1){
            bar_cnt = 0;
            __threadfence();
            bar_gen = g + 1;
        } else {
            while (bar_gen == g) { }
        }
        __threadfence();   // acquire: order post-barrier reads after flag observation
    }
    __syncthreads();
}

// ---------------- prologue: transposes + state init ----------------
__global__ void k_init(const float* __restrict__ Wq, const float* __restrict__ Wv,
                       const float* __restrict__ Wk,
                       const float* __restrict__ h0g, const float* __restrict__ h0s){
    int gt = blockIdx.x*blockDim.x + threadIdx.x, stride = gridDim.x*blockDim.x;
    for (int idx = gt; idx < E*E; idx += stride){
        int o = idx / E, i = idx - o*E;
        g_WqT[idx] = Wq[i*E + o];
        g_WvT[idx] = Wv[i*E + o];
    }
    for (int idx = gt; idx < E*E2; idx += stride){
        int o = idx / E2, i = idx - o*E2;
        g_WkT[idx] = Wk[i*E + o];
    }
    for (int idx = gt; idx < 8*E2; idx += stride) g_sst[idx] = h0s[idx % E2];  // E2 not pow2!
    for (int idx = gt; idx < E2;  idx += stride) g_ghid[idx] = h0g[idx];
}

// ---------------- prologue: WkvT[e][i] = sum_o WvT[e][o] * WkT[o][i] ----------------
__global__ void k_gemm(){
    __shared__ float As[16*64], Bs[16*64];
    int b = blockIdx.x, bm = b % 12, bn = b / 12;       // 12*24 = 288 blocks
    int tid = threadIdx.x, tx = tid % 16, ty = tid / 16;
    float acc[4][4] = {};
    for (int ko = 0; ko < E; ko += 16){
        for (int l = tid; l < 1024; l += 256){
            int m = l >> 4, kk = l & 15;
            As[kk*64 + m] = g_WvT[(bm*64 + m)*E + ko + kk];
        }
        for (int l = tid; l < 1024; l += 256){
            int kk = l >> 6, il = l & 63;
            Bs[kk*64 + il] = g_WkT[(ko + kk)*E2 + bn*64 + il];
        }
        __syncthreads();
        for (int kk = 0; kk < 16; ++kk){
            float av[4], bv[4];
#pragma unroll
            for (int r = 0; r < 4; r++) av[r] = As[kk*64 + ty*4 + r];
#pragma unroll
            for (int c = 0; c < 4; c++) bv[c] = Bs[kk*64 + tx*4 + c];
#pragma unroll
            for (int r = 0; r < 4; r++)
#pragma unroll
                for (int c = 0; c < 4; c++) acc[r][c] += av[r]*bv[c];
        }
        __syncthreads();
    }
    for (int r = 0; r < 4; r++)
        for (int c = 0; c < 4; c++)
            g_WkvT[(bm*64 + ty*4 + r)*E2 + bn*64 + tx*4 + c] = acc[r][c];
}

// ---------------- prologue: q_all, vz ----------------
__global__ void k_qall(const float* __restrict__ dialogue, const float* __restrict__ bq,
                       const float* __restrict__ bk, const float* __restrict__ bv){
    int tid = threadIdx.x, lane = tid & 31;
    int gw = blockIdx.x*8 + (tid >> 5), NW = gridDim.x*8;
    // jobs [0, 24576): (tg, o) -> 8 t's per job;  [24576, 25344): vz rows
    for (int job = gw; job < 24576 + E; job += NW){
        if (job < 24576){
            int tg = job / E, o = job - tg*E;
            const float4* wr = (const float4*)(g_WqT + o*E);
            float acc[8];
#pragma unroll
            for (int s = 0; s < 8; s++) acc[s] = 0.f;
            for (int c = lane; c < E/4; c += 32){
                float4 w = wr[c];
#pragma unroll
                for (int s = 0; s < 8; s++){
                    float4 d = ((const float4*)(dialogue + (tg*8 + s)*E))[c];
                    acc[s] += w.x*d.x + w.y*d.y + w.z*d.z + w.w*d.w;
                }
            }
#pragma unroll
            for (int s = 0; s < 8; s++){
                float r = wred(acc[s]);
                if (lane == 0) g_qall[(tg*8 + s)*E + o] = r + bq[o];
            }
        } else {
            int e = job - 24576;
            const float4* wr = (const float4*)(g_WvT + e*E);
            const float4* xr = (const float4*)bk;
            float a = 0.f;
            for (int c = lane; c < E/4; c += 32){
                float4 w = wr[c], x = xr[c];
                a += w.x*x.x + w.y*x.y + w.z*x.z + w.w*x.w;
            }
            a = wred(a);
            if (lane == 0) g_vz[e] = a + bv[e];
        }
    }
}

// ---------------- prologue: P_all, c_all (pre-scaled by 1/sqrt(E)) ----------------
__global__ void k_pall(const float* __restrict__ Wk, const float* __restrict__ bk){
    const float INVN = 0.036084391824351615f;   // 1/sqrt(768)
    int tid = threadIdx.x, lane = tid & 31;
    int gw = blockIdx.x*8 + (tid >> 5), NW = gridDim.x*8;
    // jobs [0, 49152): (tg, i) 8 t's each;  [49152, 49408): c_all
    for (int job = gw; job < 49152 + ULEN; job += NW){
        if (job < 49152){
            int tg = job / E2, i = job - tg*E2;
            const float4* wr = (const float4*)(Wk + i*E);
            float acc[8];
#pragma unroll
            for (int s = 0; s < 8; s++) acc[s] = 0.f;
            for (int c = lane; c < E/4; c += 32){
                float4 w = wr[c];
#pragma unroll
                for (int s = 0; s < 8; s++){
                    float4 q = ((const float4*)(g_qall + (tg*8 + s)*E))[c];
                    acc[s] += w.x*q.x + w.y*q.y + w.z*q.z + w.w*q.w;
                }
            }
#pragma unroll
            for (int s = 0; s < 8; s++){
                float r = wred(acc[s]);
                if (lane == 0) g_Pall[(tg*8 + s)*E2 + i] = r * INVN;
            }
        } else {
            int t = job - 49152;
            const float4* xr = (const float4*)bk;
            const float4* qr = (const float4*)(g_qall + t*E);
            float a = 0.f;
            for (int c = lane; c < E/4; c += 32){
                float4 x = xr[c], q = qr[c];
                a += x.x*q.x + x.y*q.y + x.z*q.z + x.w*q.w;
            }
            a = wred(a);
            if (lane == 0) g_call[t] = a * INVN;
        }
    }
}

// ---------------- main persistent kernel ----------------
__global__ void __launch_bounds__(NTH, 1) k_main(
    const float* __restrict__ dialogue, const int* __restrict__ speakers,
    const float* __restrict__ sWhh_f, const float* __restrict__ sbhh_f,
    const float* __restrict__ sWhh_b, const float* __restrict__ sbhh_b,
    const float* __restrict__ gWhh_f, const float* __restrict__ gbhh_f,
    const float* __restrict__ gWhh_b, const float* __restrict__ gbhh_b,
    const float* __restrict__ sWih_f, const float* __restrict__ sbih_f,
    const float* __restrict__ sWih_b, const float* __restrict__ sbih_b,
    const float* __restrict__ gWih_f, const float* __restrict__ gbih_f,
    const float* __restrict__ gWih_b, const float* __restrict__ gbih_b,
    const float* __restrict__ att0, float* __restrict__ out)
{
    __shared__ __align__(16) float sm[6144];
    const int tid  = threadIdx.x, lane = tid & 31, warp = tid >> 5;
    const int gw   = blockIdx.x*8 + warp;
    const int NW   = gridDim.x*8;
    float* out1 = out;               // global_output [U, 2E]
    float* out2 = out + ULEN*E2;     // speaker_output [U, 2E]

    for (int t = 0; t < ULEN; ++t){
        const int sp = speakers[t];
        // ======== P1 stage: hiddens (ldcg), buf[t-1], P[t] ========
        for (int i = tid; i < E2; i += NTH){
            sm[i]        = __ldcg(g_sst  + sp*E2 + i);  // [hsf | hsb]
            sm[E2 + i]   = __ldcg(g_ghid + i);          // [ghf | ghb]
            sm[3*E2 + i] = g_Pall[t*E2 + i];
        }
        if (t > 0)
            for (int i = tid; i < E2; i += NTH) sm[2*E2 + i] = g_buf[(t-1)*E2 + i];
        __syncthreads();
        const float ct = g_call[t];
        // ======== P1 jobs: 3072 gh-triples + 768 v rows + 256 scores ========
        for (int job = gw; job < 4096; job += NW){
            if (job < 3072){
                int m = job / E, e = job - m*E;
                const float *W, *bh;
                if      (m == 0){ W = sWhh_f; bh = sbhh_f; }
                else if (m == 1){ W = sWhh_b; bh = sbhh_b; }
                else if (m == 2){ W = gWhh_f; bh = gbhh_f; }
                else            { W = gWhh_b; bh = gbhh_b; }
                const float4* w0 = (const float4*)(W + e*E);
                const float4* w1 = (const float4*)(W + (E + e)*E);
                const float4* w2 = (const float4*)(W + (2*E + e)*E);
                const float4* x4 = (const float4*)(sm + m*E);
                float a0 = 0.f, a1 = 0.f, a2 = 0.f;
                for (int c = lane; c < E/4; c += 32){
                    float4 x = x4[c], wa = w0[c], wb = w1[c], wc = w2[c];
                    a0 += x.x*wa.x + x.y*wa.y + x.z*wa.z + x.w*wa.w;
                    a1 += x.x*wb.x + x.y*wb.y + x.z*wb.z + x.w*wb.w;
                    a2 += x.x*wc.x + x.y*wc.y + x.z*wc.z + x.w*wc.w;
                }
                a0 = wred(a0); a1 = wred(a1); a2 = wred(a2);
                if (lane == 0){
                    g_gh[m*E3 + e]       = a0 + bh[e];
                    g_gh[m*E3 + E + e]   = a1 + bh[E + e];
                    g_gh[m*E3 + 2*E + e] = a2 + bh[2*E + e];
                }
            } else if (job < 3840){
                if (t > 0){
                    int e = job - 3072;
                    const float4* w  = (const float4*)(g_WkvT + e*E2);
                    const float4* x4 = (const float4*)(sm + 2*E2);
                    float a = 0.f;
                    for (int c = lane; c < E2/4; c += 32){
                        float4 x = x4[c], wv = w[c];
                        a += x.x*wv.x + x.y*wv.y + x.z*wv.z + x.w*wv.w;
                    }
                    a = wred(a);
                    if (lane == 0) g_v[(t-1)*E + e] = a + g_vz[e];
                }
            } else {
                int j = job - 3840;
                if (j > t){        if (lane == 0) g_score[j] = -1e9f; }
                else if (j == t){  if (lane == 0) g_score[j] = ct; }
                else {
                    const float4* b4 = (const float4*)(g_buf + j*E2);
                    const float4* p4 = (const float4*)(sm + 3*E2);
                    float a = 0.f;
                    for (int c = lane; c < E2/4; c += 32){
                        float4 x = b4[c], p = p4[c];
                        a += x.x*p.x + x.y*p.y + x.z*p.z + x.w*p.w;
                    }
                    a = wred(a);
                    if (lane == 0) g_score[j] = a + ct;
                }
            }
        }
        gsync();
        // ======== P2: softmax (redundant per block) + att slice ========
        if (blockIdx.x < 128){
            if (t == 0){
                if (tid < 6){ int e = blockIdx.x*6 + tid; g_att[e] = att0[e]; }
            } else {
                sm[tid] = __ldcg(g_score + tid);
                __syncthreads();
                sm[512 + tid] = sm[tid];
                __syncthreads();
                for (int s = 128; s > 0; s >>= 1){
                    if (tid < s) sm[512+tid] = fmaxf(sm[512+tid], sm[512+tid+s]);
                    __syncthreads();
                }
                float mx = sm[512];
                __syncthreads();
                sm[256 + tid] = expf(sm[tid] - mx);
                sm[512 + tid] = sm[256 + tid];
                __syncthreads();
                for (int s = 128; s > 0; s >>= 1){
                    if (tid < s) sm[512+tid] += sm[512+tid+s];
                    __syncthreads();
                }
                float denom = sm[512];
                if (warp < 6){
                    int e = blockIdx.x*6 + warp;
                    float acc = 0.f;
                    for (int j = lane; j < t; j += 32) acc += sm[256 + j] * g_v[j*E + e];
                    acc = wred(acc);
                    if (lane == 0){
                        acc += sm[256 + t] * g_vz[e];   // j == t row is k_zero/v_zero
                        g_att[e] = acc / denom;
                    }
                }
            }
        }
        gsync();
        // ======== P3 stage: x = [att | u] ========
        for (int i = tid; i < E; i += NTH){
            sm[i]     = __ldcg(g_att + i);
            sm[E + i] = dialogue[t*E + i];
        }
        __syncthreads();
        // ======== P3 jobs: 1536 speaker gate-triples ========
        for (int job = gw; job < E2; job += NW){
            int dir = job / E, e = job - dir*E;
            const float* W  = dir ? sWih_b : sWih_f;
            const float* bi = dir ? sbih_b : sbih_f;
            const float4* w0 = (const float4*)(W + e*E2);
            const float4* w1 = (const float4*)(W + (E + e)*E2);
            const float4* w2 = (const float4*)(W + (2*E + e)*E2);
            const float4* x4 = (const float4*)sm;
            float a0 = 0.f, a1 = 0.f, a2 = 0.f;
            for (int c = lane; c < E2/4; c += 32){
                float4 x = x4[c], wa = w0[c], wb = w1[c], wc = w2[c];
                a0 += x.x*wa.x + x.y*wa.y + x.z*wa.z + x.w*wa.w;
                a1 += x.x*wb.x + x.y*wb.y + x.z*wb.z + x.w*wb.w;
                a2 += x.x*wc.x + x.y*wc.y + x.z*wc.z + x.w*wc.w;
            }
            a0 = wred(a0); a1 = wred(a1); a2 = wred(a2);
            if (lane == 0){
                int gi = dir*E3;
                float r  = sigm(a0 + bi[e]       + __ldcg(g_gh + gi + e));
                float z  = sigm(a1 + bi[E + e]   + __ldcg(g_gh + gi + E + e));
                float n  = tanhf(a2 + bi[2*E + e] + r*__ldcg(g_gh + gi + 2*E + e));
                float hp = __ldcg(g_sst + sp*E2 + dir*E + e);
                float h  = (1.0f - z)*n + z*hp;
                g_sst[sp*E2 + dir*E + e] = h;
                float so = h + sm[dir*E + e];
                g_so[dir*E + e] = so;
                out2[t*E2 + dir*E + e] = so;
            }
        }
        gsync();
        // ======== P4 stage: x = [so | u] ========
        for (int i = tid; i < E2; i += NTH) sm[i] = __ldcg(g_so + i);
        for (int i = tid; i < E;  i += NTH) sm[E2 + i] = dialogue[t*E + i];
        __syncthreads();
        // ======== P4 jobs: 1536 global gate-triples ========
        for (int job = gw; job < E2; job += NW){
            int dir = job / E, e = job - dir*E;
            const float* W  = dir ? gWih_b : gWih_f;
            const float* bi = dir ? gbih_b : gbih_f;
            const float4* w0 = (const float4*)(W + e*E3);
            const float4* w1 = (const float4*)(W + (E + e)*E3);
            const float4* w2 = (const float4*)(W + (2*E + e)*E3);
            const float4* x4 = (const float4*)sm;
            float a0 = 0.f, a1 = 0.f, a2 = 0.f;
            for (int c = lane; c < E3/4; c += 32){
                float4 x = x4[c], wa = w0[c], wb = w1[c], wc = w2[c];
                a0 += x.x*wa.x + x.y*wa.y + x.z*wa.z + x.w*wa.w;
                a1 += x.x*wb.x + x.y*wb.y + x.z*wb.z + x.w*wb.w;
                a2 += x.x*wc.x + x.y*wc.y + x.z*wc.z + x.w*wc.w;
            }
            a0 = wred(a0); a1 = wred(a1); a2 = wred(a2);
            if (lane == 0){
                int gi = (2 + dir)*E3;
                float r  = sigm(a0 + bi[e]       + __ldcg(g_gh + gi + e));
                float z  = sigm(a1 + bi[E + e]   + __ldcg(g_gh + gi + E + e));
                float n  = tanhf(a2 + bi[2*E + e] + r*__ldcg(g_gh + gi + 2*E + e));
                float hp = __ldcg(g_ghid + dir*E + e);
                float h  = (1.0f - z)*n + z*hp;
                g_ghid[dir*E + e]       = h;
                g_buf [t*E2 + dir*E + e] = h;
                out1  [t*E2 + dir*E + e] = h;
            }
        }
        gsync();
    }
}

extern "C" void kernel_launch(void* const* d_in, const int* in_sizes, int n_in,
                              void* d_out, int out_size){
    (void)in_sizes; (void)n_in; (void)out_size;
    const float* dialogue = (const float*)d_in[0];
    const int*   speakers = (const int*)  d_in[1];
    const float* Wq = (const float*)d_in[2];  const float* bq = (const float*)d_in[3];
    const float* Wk = (const float*)d_in[4];  const float* bk = (const float*)d_in[5];
    const float* Wv = (const float*)d_in[6];  const float* bv = (const float*)d_in[7];
    const float* sWih_f = (const float*)d_in[8];  const float* sWhh_f = (const float*)d_in[9];
    const float* sbih_f = (const float*)d_in[10]; const float* sbhh_f = (const float*)d_in[11];
    const float* sWih_b = (const float*)d_in[12]; const float* sWhh_b = (const float*)d_in[13];
    const float* sbih_b = (const float*)d_in[14]; const float* sbhh_b = (const float*)d_in[15];
    const float* gWih_f = (const float*)d_in[16]; const float* gWhh_f = (const float*)d_in[17];
    const float* gbih_f = (const float*)d_in[18]; const float* gbhh_f = (const float*)d_in[19];
    const float* gWih_b = (const float*)d_in[20]; const float* gWhh_b = (const float*)d_in[21];
    const float* gbih_b = (const float*)d_in[22]; const float* gbhh_b = (const float*)d_in[23];
    const float* h0_global  = (const float*)d_in[24];
    const float* h0_speaker = (const float*)d_in[25];
    const float* att0       = (const float*)d_in[26];
    float* out = (float*)d_out;

    k_init<<<NB, NTH>>>(Wq, Wv, Wk, h0_global, h0_speaker);
    k_gemm<<<288, NTH>>>();
    k_qall<<<NB, NTH>>>(dialogue, bq, bk, bv);
    k_pall<<<NB, NTH>>>(Wk, bk);
    k_main<<<NB, NTH>>>(dialogue, speakers,
                        sWhh_f, sbhh_f, sWhh_b, sbhh_b,
                        gWhh_f, gbhh_f, gWhh_b, gbhh_b,
                        sWih_f, sbih_f, sWih_b, sbih_b,
                        gWih_f, gbih_f, gWih_b, gbih_b,
                        att0, out);
}

// round 9
// speedup vs baseline: 1.3373x; 1.3373x over previous
#include <cuda_runtime.h>
#include <math.h>

#define E    768
#define E2   1536
#define E3   2304
#define ULEN 256
#define NB   148
#define NTM  1024
#define NW_MAIN (NB*32)
#define INVN 0.036084391824351615f

// ---------------- device scratch (no allocations allowed) ----------------
__device__ __align__(16) float g_WvT [E*E];      // Wv^T [e][o]
__device__ __align__(16) float g_WkT [E*E2];     // Wk^T [o][i]
__device__ __align__(16) float g_WkvT[E*E2];     // [e][i]
__device__ __align__(16) float g_qall[ULEN*E];
__device__ __align__(16) float g_Pall[ULEN*E2];  // pre-scaled by 1/sqrt(E)
__device__ __align__(16) float g_call[ULEN];     // pre-scaled
__device__ __align__(16) float g_vz  [E];
__device__ __align__(16) float g_vT  [E*ULEN];   // v transposed [e][j]
__device__ __align__(16) float g_score[ULEN];
__device__ __align__(16) float g_att [E];
__device__ __align__(16) float g_gh  [4*E3];     // Whh@h + bhh for {sf, sb, gf, gb}
__device__ __align__(16) float g_so  [E2];
__device__ __align__(16) float g_sst [8*E2];     // speaker states [spk][dir][e]
__device__ __align__(16) float g_ghid[E2];       // global GRU carry [dir][e]
__device__ __align__(16) float g_buf [ULEN*E2];
__device__ unsigned           bar_cnt;
__device__ volatile unsigned  bar_gen;

__device__ __forceinline__ float wred(float v){
#pragma unroll
    for (int o = 16; o; o >>= 1) v += __shfl_xor_sync(0xffffffffu, v, o);
    return v;
}
__device__ __forceinline__ float sigm(float x){ return 1.0f/(1.0f + expf(-x)); }

__device__ __forceinline__ void gsync(){
    __syncthreads();
    if (threadIdx.x == 0){
        __threadfence();
        unsigned g = bar_gen;
        if (atomicAdd(&bar_cnt, 1u) == gridDim.x - 1){
            bar_cnt = 0;
            __threadfence();
            bar_gen = g + 1;
        } else {
            while (bar_gen == g) { }
        }
        __threadfence();
    }
    __syncthreads();
}

// ---------------- prologue: transposes + state init ----------------
__global__ void k_init(const float* __restrict__ Wv, const float* __restrict__ Wk,
                       const float* __restrict__ h0g, const float* __restrict__ h0s){
    int gt = blockIdx.x*blockDim.x + threadIdx.x, stride = gridDim.x*blockDim.x;
    for (int idx = gt; idx < E*E; idx += stride){
        int o = idx / E, i = idx - o*E;
        g_WvT[idx] = Wv[i*E + o];
    }
    for (int idx = gt; idx < E*E2; idx += stride){
        int o = idx / E2, i = idx - o*E2;
        g_WkT[idx] = Wk[i*E + o];
    }
    for (int idx = gt; idx < 8*E2; idx += stride) g_sst[idx] = h0s[idx % E2];
    for (int idx = gt; idx < E2;  idx += stride) g_ghid[idx] = h0g[idx];
}

// ---------------- generic 64x64 tiled GEMM body: C = scale*(A@B) (+ bias[col]) ----------------
__device__ __forceinline__ void gemm_body(const float* __restrict__ A,
                                          const float* __restrict__ B,
                                          const float* __restrict__ bias,
                                          float* __restrict__ C,
                                          int M, int N, int K, float scale){
    __shared__ float As[16*64], Bs[16*64];
    int bn = blockIdx.x, bm = blockIdx.y;
    int tid = threadIdx.x, tx = tid % 16, ty = tid / 16;
    float acc[4][4] = {};
    for (int ko = 0; ko < K; ko += 16){
        for (int l = tid; l < 1024; l += 256){
            int m = l >> 4, kk = l & 15;
            As[kk*64 + m] = A[(bm*64 + m)*K + ko + kk];
        }
        for (int l = tid; l < 1024; l += 256){
            int kk = l >> 6, il = l & 63;
            Bs[kk*64 + il] = B[(ko + kk)*N + bn*64 + il];
        }
        __syncthreads();
#pragma unroll
        for (int kk = 0; kk < 16; ++kk){
            float av[4], bv[4];
#pragma unroll
            for (int r = 0; r < 4; r++) av[r] = As[kk*64 + ty*4 + r];
#pragma unroll
            for (int c = 0; c < 4; c++) bv[c] = Bs[kk*64 + tx*4 + c];
#pragma unroll
            for (int r = 0; r < 4; r++)
#pragma unroll
                for (int c = 0; c < 4; c++) acc[r][c] += av[r]*bv[c];
        }
        __syncthreads();
    }
#pragma unroll
    for (int r = 0; r < 4; r++)
#pragma unroll
        for (int c = 0; c < 4; c++){
            int col = bn*64 + tx*4 + c;
            float v = acc[r][c]*scale;
            if (bias) v += bias[col];
            C[(bm*64 + ty*4 + r)*N + col] = v;
        }
}

__global__ void k_gemm_q(const float* __restrict__ dialogue, const float* __restrict__ Wq,
                         const float* __restrict__ bq){
    gemm_body(dialogue, Wq, bq, g_qall, ULEN, E, E, 1.0f);
}
__global__ void k_gemm_kv(){
    gemm_body(g_WvT, g_WkT, 0, g_WkvT, E, E2, E, 1.0f);
}
__global__ void k_gemm_p(){
    gemm_body(g_qall, g_WkT, 0, g_Pall, ULEN, E2, E, INVN);
}

// ---------------- prologue: vz, c_all ----------------
__global__ void k_misc(const float* __restrict__ bk, const float* __restrict__ bv){
    int tid = threadIdx.x, lane = tid & 31;
    int gw = blockIdx.x*8 + (tid >> 5), NW = gridDim.x*8;
    for (int job = gw; job < E + ULEN; job += NW){
        if (job < E){
            int e = job;
            const float4* wr = (const float4*)(g_WvT + e*E);
            const float4* xr = (const float4*)bk;
            float a = 0.f;
            for (int c = lane; c < E/4; c += 32){
                float4 w = wr[c], x = xr[c];
                a += w.x*x.x + w.y*x.y + w.z*x.z + w.w*x.w;
            }
            a = wred(a);
            if (lane == 0) g_vz[e] = a + bv[e];
        } else {
            int t = job - E;
            const float4* xr = (const float4*)bk;
            const float4* qr = (const float4*)(g_qall + t*E);
            float a = 0.f;
            for (int c = lane; c < E/4; c += 32){
                float4 x = xr[c], q = qr[c];
                a += x.x*q.x + x.y*q.y + x.z*q.z + x.w*q.w;
            }
            a = wred(a);
            if (lane == 0) g_call[t] = a * INVN;
        }
    }
}

// ---------------- main persistent kernel ----------------
__global__ void __launch_bounds__(NTM, 1) k_main(
    const float* __restrict__ dialogue, const int* __restrict__ speakers,
    const float* __restrict__ sWhh_f, const float* __restrict__ sbhh_f,
    const float* __restrict__ sWhh_b, const float* __restrict__ sbhh_b,
    const float* __restrict__ gWhh_f, const float* __restrict__ gbhh_f,
    const float* __restrict__ gWhh_b, const float* __restrict__ gbhh_b,
    const float* __restrict__ sWih_f, const float* __restrict__ sbih_f,
    const float* __restrict__ sWih_b, const float* __restrict__ sbih_b,
    const float* __restrict__ gWih_f, const float* __restrict__ gbih_f,
    const float* __restrict__ gWih_b, const float* __restrict__ gbih_b,
    const float* __restrict__ att0, float* __restrict__ out)
{
    __shared__ __align__(16) float sm[6144];
    __shared__ float s_sc[ULEN], s_prob[ULEN];
    __shared__ float s_red, s_den;
    __shared__ float smP[16*6];
    const int tid  = threadIdx.x, lane = tid & 31, warp = tid >> 5;
    const int gw   = blockIdx.x*32 + warp;
    const int pairg = blockIdx.x*16 + (warp >> 1);
    const int half  = warp & 1;
    float* out1 = out;               // global_output [U, 2E]
    float* out2 = out + ULEN*E2;     // speaker_output [U, 2E]

    for (int t = 0; t < ULEN; ++t){
        const int sp = speakers[t];
        // ======== P1 stage: hiddens (ldcg), buf[t-1], P[t] ========
        for (int i = tid; i < E2; i += NTM){
            sm[i]        = __ldcg(g_sst  + sp*E2 + i);  // [hsf | hsb]
            sm[E2 + i]   = __ldcg(g_ghid + i);          // [ghf | ghb]
            sm[3*E2 + i] = g_Pall[t*E2 + i];
        }
        if (t > 0)
            for (int i = tid; i < E2; i += NTM) sm[2*E2 + i] = g_buf[(t-1)*E2 + i];
        __syncthreads();
        const float ct = g_call[t];
        // ======== P1 jobs: 3072 gh-triples + 768 v rows + 256 scores ========
        for (int job = gw; job < 4096; job += NW_MAIN){
            if (job < 3072){
                int m = job / E, e = job - m*E;
                const float *W, *bh;
                if      (m == 0){ W = sWhh_f; bh = sbhh_f; }
                else if (m == 1){ W = sWhh_b; bh = sbhh_b; }
                else if (m == 2){ W = gWhh_f; bh = gbhh_f; }
                else            { W = gWhh_b; bh = gbhh_b; }
                const float4* w0 = (const float4*)(W + e*E);
                const float4* w1 = (const float4*)(W + (E + e)*E);
                const float4* w2 = (const float4*)(W + (2*E + e)*E);
                const float4* x4 = (const float4*)(sm + m*E);
                float a0 = 0.f, a1 = 0.f, a2 = 0.f;
                for (int c = lane; c < E/4; c += 32){
                    float4 x = x4[c], wa = w0[c], wb = w1[c], wc = w2[c];
                    a0 += x.x*wa.x + x.y*wa.y + x.z*wa.z + x.w*wa.w;
                    a1 += x.x*wb.x + x.y*wb.y + x.z*wb.z + x.w*wb.w;
                    a2 += x.x*wc.x + x.y*wc.y + x.z*wc.z + x.w*wc.w;
                }
                a0 = wred(a0); a1 = wred(a1); a2 = wred(a2);
                if (lane == 0){
                    g_gh[m*E3 + e]       = a0 + bh[e];
                    g_gh[m*E3 + E + e]   = a1 + bh[E + e];
                    g_gh[m*E3 + 2*E + e] = a2 + bh[2*E + e];
                }
            } else if (job < 3840){
                if (t > 0){
                    int e = job - 3072;
                    const float4* w  = (const float4*)(g_WkvT + e*E2);
                    const float4* x4 = (const float4*)(sm + 2*E2);
                    float a = 0.f;
                    for (int c = lane; c < E2/4; c += 32){
                        float4 x = x4[c], wv = w[c];
                        a += x.x*wv.x + x.y*wv.y + x.z*wv.z + x.w*wv.w;
                    }
                    a = wred(a);
                    if (lane == 0) g_vT[e*ULEN + (t-1)] = a + g_vz[e];
                }
            } else {
                int j = job - 3840;
                if (j > t){        if (lane == 0) g_score[j] = -1e9f; }
                else if (j == t){  if (lane == 0) g_score[j] = ct; }
                else {
                    const float4* b4 = (const float4*)(g_buf + j*E2);
                    const float4* p4 = (const float4*)(sm + 3*E2);
                    float a = 0.f;
                    for (int c = lane; c < E2/4; c += 32){
                        float4 x = b4[c], p = p4[c];
                        a += x.x*p.x + x.y*p.y + x.z*p.z + x.w*p.w;
                    }
                    a = wred(a);
                    if (lane == 0) g_score[j] = a + ct;
                }
            }
        }
        gsync();
        // ======== P2: softmax (redundant per block) + att slice ========
        if (t == 0){
            if (blockIdx.x == 0)
                for (int i = tid; i < E; i += NTM) g_att[i] = att0[i];
        } else if (blockIdx.x < 128){
            if (tid < ULEN) s_sc[tid] = __ldcg(g_score + tid);
            __syncthreads();
            if (warp == 0){
                float m = -1e30f;
                for (int k2 = lane; k2 < ULEN; k2 += 32) m = fmaxf(m, s_sc[k2]);
#pragma unroll
                for (int o = 16; o; o >>= 1) m = fmaxf(m, __shfl_xor_sync(0xffffffffu, m, o));
                if (lane == 0) s_red = m;
            }
            __syncthreads();
            float mx = s_red;
            if (tid < ULEN) s_prob[tid] = expf(s_sc[tid] - mx);
            __syncthreads();
            if (warp == 0){
                float sme = 0.f;
                for (int k2 = lane; k2 < ULEN; k2 += 32) sme += s_prob[k2];
                sme = wred(sme);
                if (lane == 0) s_den = sme;
            }
            __syncthreads();
            if (warp < 6){
                int e = blockIdx.x*6 + warp;
                float acc = 0.f;
                for (int j = lane; j < t; j += 32) acc += s_prob[j] * __ldcg(g_vT + e*ULEN + j);
                acc = wred(acc);
                if (lane == 0) g_att[e] = (acc + s_prob[t]*g_vz[e]) / s_den;
            }
        }
        gsync();
        // ======== P3 stage: x = [att | u] ========
        for (int i = tid; i < E; i += NTM){
            sm[i]     = __ldcg(g_att + i);
            sm[E + i] = dialogue[t*E + i];
        }
        __syncthreads();
        // ======== P3: 1536 speaker gate-triples, 2-warp K-split ========
        if (pairg < E2){
            int dir = pairg / E, e = pairg - dir*E;
            const float* W = dir ? sWih_b : sWih_f;
            const float4* w0 = (const float4*)(W + e*E2);
            const float4* w1 = (const float4*)(W + (E + e)*E2);
            const float4* w2 = (const float4*)(W + (2*E + e)*E2);
            const float4* x4 = (const float4*)sm;
            float a0 = 0.f, a1 = 0.f, a2 = 0.f;
            int base = half*192;
            for (int c = base + lane; c < base + 192; c += 32){
                float4 x = x4[c], wa = w0[c], wb = w1[c], wc = w2[c];
                a0 += x.x*wa.x + x.y*wa.y + x.z*wa.z + x.w*wa.w;
                a1 += x.x*wb.x + x.y*wb.y + x.z*wb.z + x.w*wb.w;
                a2 += x.x*wc.x + x.y*wc.y + x.z*wc.z + x.w*wc.w;
            }
            a0 = wred(a0); a1 = wred(a1); a2 = wred(a2);
            if (lane == 0){
                int pl = (warp >> 1)*6 + half*3;
                smP[pl] = a0; smP[pl+1] = a1; smP[pl+2] = a2;
            }
        }
        __syncthreads();
        if (pairg < E2 && half == 0 && lane == 0){
            int dir = pairg / E, e = pairg - dir*E;
            const float* bi = dir ? sbih_b : sbih_f;
            int pl = (warp >> 1)*6;
            float a0 = smP[pl]   + smP[pl+3];
            float a1 = smP[pl+1] + smP[pl+4];
            float a2 = smP[pl+2] + smP[pl+5];
            int gi = dir*E3;
            float r  = sigm(a0 + bi[e]        + __ldcg(g_gh + gi + e));
            float z  = sigm(a1 + bi[E + e]    + __ldcg(g_gh + gi + E + e));
            float n  = tanhf(a2 + bi[2*E + e] + r*__ldcg(g_gh + gi + 2*E + e));
            float hp = __ldcg(g_sst + sp*E2 + dir*E + e);
            float h  = (1.0f - z)*n + z*hp;
            g_sst[sp*E2 + dir*E + e] = h;
            float so = h + sm[dir*E + e];
            g_so[dir*E + e] = so;
            out2[t*E2 + dir*E + e] = so;
        }
        gsync();
        // ======== P4 stage: x = [so | u] ========
        for (int i = tid; i < E2; i += NTM) sm[i] = __ldcg(g_so + i);
        for (int i = tid; i < E;  i += NTM) sm[E2 + i] = dialogue[t*E + i];
        __syncthreads();
        // ======== P4: 1536 global gate-triples, 2-warp K-split ========
        if (pairg < E2){
            int dir = pairg / E, e = pairg - dir*E;
            const float* W = dir ? gWih_b : gWih_f;
            const float4* w0 = (const float4*)(W + e*E3);
            const float4* w1 = (const float4*)(W + (E + e)*E3);
            const float4* w2 = (const float4*)(W + (2*E + e)*E3);
            const float4* x4 = (const float4*)sm;
            float a0 = 0.f, a1 = 0.f, a2 = 0.f;
            int base = half*288;
            for (int c = base + lane; c < base + 288; c += 32){
                float4 x = x4[c], wa = w0[c], wb = w1[c], wc = w2[c];
                a0 += x.x*wa.x + x.y*wa.y + x.z*wa.z + x.w*wa.w;
                a1 += x.x*wb.x + x.y*wb.y + x.z*wb.z + x.w*wb.w;
                a2 += x.x*wc.x + x.y*wc.y + x.z*wc.z + x.w*wc.w;
            }
            a0 = wred(a0); a1 = wred(a1); a2 = wred(a2);
            if (lane == 0){
                int pl = (warp >> 1)*6 + half*3;
                smP[pl] = a0; smP[pl+1] = a1; smP[pl+2] = a2;
            }
        }
        __syncthreads();
        if (pairg < E2 && half == 0 && lane == 0){
            int dir = pairg / E, e = pairg - dir*E;
            const float* bi = dir ? gbih_b : gbih_f;
            int pl = (warp >> 1)*6;
            float a0 = smP[pl]   + smP[pl+3];
            float a1 = smP[pl+1] + smP[pl+4];
            float a2 = smP[pl+2] + smP[pl+5];
            int gi = (2 + dir)*E3;
            float r  = sigm(a0 + bi[e]        + __ldcg(g_gh + gi + e));
            float z  = sigm(a1 + bi[E + e]    + __ldcg(g_gh + gi + E + e));
            float n  = tanhf(a2 + bi[2*E + e] + r*__ldcg(g_gh + gi + 2*E + e));
            float hp = __ldcg(g_ghid + dir*E + e);
            float h  = (1.0f - z)*n + z*hp;
            g_ghid[dir*E + e]        = h;
            g_buf [t*E2 + dir*E + e] = h;
            out1  [t*E2 + dir*E + e] = h;
        }
        gsync();
    }
}

extern "C" void kernel_launch(void* const* d_in, const int* in_sizes, int n_in,
                              void* d_out, int out_size){
    (void)in_sizes; (void)n_in; (void)out_size;
    const float* dialogue = (const float*)d_in[0];
    const int*   speakers = (const int*)  d_in[1];
    const float* Wq = (const float*)d_in[2];  const float* bq = (const float*)d_in[3];
    const float* Wk = (const float*)d_in[4];  const float* bk = (const float*)d_in[5];
    const float* Wv = (const float*)d_in[6];  const float* bv = (const float*)d_in[7];
    const float* sWih_f = (const float*)d_in[8];  const float* sWhh_f = (const float*)d_in[9];
    const float* sbih_f = (const float*)d_in[10]; const float* sbhh_f = (const float*)d_in[11];
    const float* sWih_b = (const float*)d_in[12]; const float* sWhh_b = (const float*)d_in[13];
    const float* sbih_b = (const float*)d_in[14]; const float* sbhh_b = (const float*)d_in[15];
    const float* gWih_f = (const float*)d_in[16]; const float* gWhh_f = (const float*)d_in[17];
    const float* gbih_f = (const float*)d_in[18]; const float* gbhh_f = (const float*)d_in[19];
    const float* gWih_b = (const float*)d_in[20]; const float* gWhh_b = (const float*)d_in[21];
    const float* gbih_b = (const float*)d_in[22]; const float* gbhh_b = (const float*)d_in[23];
    const float* h0_global  = (const float*)d_in[24];
    const float* h0_speaker = (const float*)d_in[25];
    const float* att0       = (const float*)d_in[26];
    float* out = (float*)d_out;

    k_init   <<<NB, 256>>>(Wv, Wk, h0_global, h0_speaker);
    k_gemm_q <<<dim3(E/64,  ULEN/64), 256>>>(dialogue, Wq, bq);
    k_gemm_kv<<<dim3(E2/64, E/64),    256>>>();
    k_gemm_p <<<dim3(E2/64, ULEN/64), 256>>>();
    k_misc   <<<NB, 256>>>(bk, bv);
    k_main   <<<NB, NTM>>>(dialogue, speakers,
                           sWhh_f, sbhh_f, sWhh_b, sbhh_b,
                           gWhh_f, gbhh_f, gWhh_b, gbhh_b,
                           sWih_f, sbih_f, sWih_b, sbih_b,
                           gWih_f, gbih_f, gWih_b, gbih_b,
                           att0, out);
}